// round 1
// baseline (speedup 1.0000x reference)
#include <cuda_runtime.h>
#include <cuda_bf16.h>
#include <cstdint>

// Problem constants
#define BB 8
#define NN 192
#define DD 768
#define HH 150

// k2 tiling
#define TI 16          // i-rows per tile
#define TJ 8           // j-rows per tile
#define NPAIR (TI*TJ)  // 128 pairs per block
#define HP 76          // h-units per half-thread (padded from 75)
#define DCH 64         // d-chunk for W1c streaming
#define WPITCH 152     // padded weight-chunk row pitch (2*HP)

// Scratch (device globals: allocation-free rule)
__device__ float g_A[BB * NN * HH];   // E @ W1a + b1, per (b,i,h)
__device__ float g_B[BB * NN * HH];   // E @ W1b,     per (b,j,h)
__device__ float g_S[BB * NN * NN];   // pair scores s(b,i,j), j<i

// ---------------------------------------------------------------------------
// k1: precompute A = E@W1a + b1 and Bv = E@W1b.
// grid = 192 blocks (8 rows each), 160 threads (h = tid, active h<150).
// ---------------------------------------------------------------------------
__global__ void k1_precompute(const float* __restrict__ E,
                              const float* __restrict__ W1,
                              const float* __restrict__ b1) {
    __shared__ float sE[8][DD];
    const int row0 = blockIdx.x * 8;           // global row in [0, B*N)
    const int tid = threadIdx.x;

    for (int idx = tid; idx < 8 * DD; idx += blockDim.x) {
        int r = idx / DD, d = idx % DD;
        sE[r][d] = E[(size_t)(row0 + r) * DD + d];
    }
    __syncthreads();

    const int h = tid;
    if (h < HH) {
        float accA[8], accB[8];
        float bias = __ldg(b1 + h);
#pragma unroll
        for (int r = 0; r < 8; r++) { accA[r] = bias; accB[r] = 0.f; }
        for (int d = 0; d < DD; d++) {
            float wa = __ldg(W1 + (size_t)d * HH + h);
            float wb = __ldg(W1 + (size_t)(DD + d) * HH + h);
#pragma unroll
            for (int r = 0; r < 8; r++) {
                float e = sE[r][d];
                accA[r] += e * wa;
                accB[r] += e * wb;
            }
        }
#pragma unroll
        for (int r = 0; r < 8; r++) {
            g_A[(size_t)(row0 + r) * HH + h] = accA[r];
            g_B[(size_t)(row0 + r) * HH + h] = accB[r];
        }
    }
}

// ---------------------------------------------------------------------------
// k2: fused pair MLP. grid = (12 i-tiles, 24 j-tiles, 8 batches), 256 threads.
// Thread t: pair p = t>>1 (li = p>>3, lj = p&7), half = t&1 owns HP=76 h-units.
// ---------------------------------------------------------------------------
__global__ __launch_bounds__(256, 1)
void k2_pairs(const float* __restrict__ E,
              const float* __restrict__ W1,   // (3D, H)
              const float* __restrict__ W2,   // (H, H)
              const float* __restrict__ b2,
              const float* __restrict__ W3,   // (H, 1)
              const float* __restrict__ b3) {
    const int ti = blockIdx.x;
    const int tj = blockIdx.y;
    const int bz = blockIdx.z;
    // skip tiles entirely above the strict-lower triangle
    if (tj * TJ >= ti * TI + TI - 1) return;

    extern __shared__ float smem[];
    float* sEi = smem;                    // 16*768 = 12288
    float* sEj = sEi + TI * DD;           //  8*768 =  6144
    float* sW  = sEj + TJ * DD;           // 64*152 =  9728 (W1c / W2 chunks)
    float* sH1 = sW + DCH * WPITCH;       // 128*151 = 19328
    float* sW3 = sH1 + NPAIR * 151;       // 152

    const int tid = threadIdx.x;
    const int p = tid >> 1;
    const int half = tid & 1;
    const int li = p >> 3;
    const int lj = p & 7;
    const int i = ti * TI + li;
    const int j = tj * TJ + lj;
    const int hbase = half * HP;

    // load E tiles (rows are contiguous in global)
    const float* Eb = E + (size_t)bz * NN * DD;
    {
        const float4* src = reinterpret_cast<const float4*>(Eb + (size_t)(ti * TI) * DD);
        float4* dst = reinterpret_cast<float4*>(sEi);
        for (int idx = tid; idx < TI * DD / 4; idx += 256) dst[idx] = src[idx];
        src = reinterpret_cast<const float4*>(Eb + (size_t)(tj * TJ) * DD);
        dst = reinterpret_cast<float4*>(sEj);
        for (int idx = tid; idx < TJ * DD / 4; idx += 256) dst[idx] = src[idx];
        for (int idx = tid; idx < WPITCH; idx += 256)
            sW3[idx] = (idx < HH) ? __ldg(W3 + idx) : 0.f;
    }

    // layer-1 accumulators, seeded with A[i,h] + Bv[j,h] (b1 already in A)
    float acc[HP];
    {
        const float* Ap = g_A + ((size_t)bz * NN + i) * HH;
        const float* Bp = g_B + ((size_t)bz * NN + j) * HH;
#pragma unroll
        for (int g = 0; g < HP; g++) {
            int hc = hbase + g;
            acc[g] = (hc < HH) ? (__ldg(Ap + hc) + __ldg(Bp + hc)) : 0.f;
        }
    }

    // layer 1: acc[h] += sum_d (ei[d]*ej[d]) * W1c[d,h], streamed in d-chunks
    const float* W1c = W1 + (size_t)(2 * DD) * HH;
    for (int dc = 0; dc < DD; dc += DCH) {
        __syncthreads();
        for (int idx = tid; idx < DCH * WPITCH; idx += 256) {
            int r = idx / WPITCH, c = idx % WPITCH;
            sW[idx] = (c < HH) ? __ldg(W1c + (size_t)(dc + r) * HH + c) : 0.f;
        }
        __syncthreads();
        const float* ei = sEi + li * DD + dc;
        const float* ej = sEj + lj * DD + dc;
#pragma unroll 2
        for (int d4 = 0; d4 < DCH / 4; d4++) {
            float4 a = *reinterpret_cast<const float4*>(ei + d4 * 4);
            float4 b = *reinterpret_cast<const float4*>(ej + d4 * 4);
            float pr[4] = {a.x * b.x, a.y * b.y, a.z * b.z, a.w * b.w};
#pragma unroll
            for (int dd = 0; dd < 4; dd++) {
                const float4* w4 = reinterpret_cast<const float4*>(
                    sW + (d4 * 4 + dd) * WPITCH + hbase);
                float pv = pr[dd];
#pragma unroll
                for (int g4 = 0; g4 < HP / 4; g4++) {
                    float4 w = w4[g4];
                    acc[g4 * 4 + 0] += pv * w.x;
                    acc[g4 * 4 + 1] += pv * w.y;
                    acc[g4 * 4 + 2] += pv * w.z;
                    acc[g4 * 4 + 3] += pv * w.w;
                }
            }
        }
    }

    // relu + stage h1 to smem (stride 151, conflict-free)
    __syncthreads();
#pragma unroll
    for (int g = 0; g < HP; g++) {
        int hc = hbase + g;
        if (hc < HH) sH1[p * 151 + hc] = fmaxf(acc[g], 0.f);
    }

    // layer 2: acc2[g] = b2 + sum_k h1[k] * W2[k, hbase+g]
    float acc2[HP];
#pragma unroll
    for (int g = 0; g < HP; g++) {
        int hc = hbase + g;
        acc2[g] = (hc < HH) ? __ldg(b2 + hc) : 0.f;
    }
    for (int kc = 0; kc < HH; kc += DCH) {
        int ksz = min(DCH, HH - kc);
        __syncthreads();
        for (int idx = tid; idx < ksz * WPITCH; idx += 256) {
            int r = idx / WPITCH, c = idx % WPITCH;
            sW[idx] = (c < HH) ? __ldg(W2 + (size_t)(kc + r) * HH + c) : 0.f;
        }
        __syncthreads();
        for (int kk = 0; kk < ksz; kk++) {
            float hv = sH1[p * 151 + kc + kk];
            const float4* w4 = reinterpret_cast<const float4*>(sW + kk * WPITCH + hbase);
#pragma unroll
            for (int g4 = 0; g4 < HP / 4; g4++) {
                float4 w = w4[g4];
                acc2[g4 * 4 + 0] += hv * w.x;
                acc2[g4 * 4 + 1] += hv * w.y;
                acc2[g4 * 4 + 2] += hv * w.z;
                acc2[g4 * 4 + 3] += hv * w.w;
            }
        }
    }

    // layer 3: relu(acc2) . W3, combine halves via shfl
    float sp = 0.f;
#pragma unroll
    for (int g = 0; g < HP; g++) {
        float h2 = fmaxf(acc2[g], 0.f);
        sp += h2 * sW3[hbase + g];
    }
    sp += __shfl_xor_sync(0xffffffffu, sp, 1);

    if (half == 0 && j < i) {
        g_S[((size_t)bz * NN + i) * NN + j] = sp + __ldg(b3);
    }
}

// ---------------------------------------------------------------------------
// k3: per-row tril softmax. grid (192, 8), 192 threads.
// Row i: logits s(i,j) for j<i, 0 at j=i, -inf above; PAD=-1000 above diag.
// ---------------------------------------------------------------------------
__global__ void k3_softmax(float* __restrict__ out) {
    const int i = blockIdx.x;
    const int b = blockIdx.y;
    const int j = threadIdx.x;

    float val;
    if (j < i)       val = g_S[((size_t)b * NN + i) * NN + j];
    else if (j == i) val = 0.f;
    else             val = -1e30f;

    __shared__ float red[6];
    // max reduce
    float m = val;
#pragma unroll
    for (int o = 16; o; o >>= 1) m = fmaxf(m, __shfl_xor_sync(0xffffffffu, m, o));
    if ((j & 31) == 0) red[j >> 5] = m;
    __syncthreads();
    float M = fmaxf(fmaxf(fmaxf(red[0], red[1]), fmaxf(red[2], red[3])),
                    fmaxf(red[4], red[5]));
    __syncthreads();

    float e = (j <= i) ? expf(val - M) : 0.f;
    float s = e;
#pragma unroll
    for (int o = 16; o; o >>= 1) s += __shfl_xor_sync(0xffffffffu, s, o);
    if ((j & 31) == 0) red[j >> 5] = s;
    __syncthreads();
    float S = red[0] + red[1] + red[2] + red[3] + red[4] + red[5];

    out[((size_t)b * NN + i) * NN + j] = (j <= i) ? (e / S) : -1000.0f;
}

// ---------------------------------------------------------------------------
extern "C" void kernel_launch(void* const* d_in, const int* in_sizes, int n_in,
                              void* d_out, int out_size) {
    const float* E  = (const float*)d_in[0];
    const float* W1 = (const float*)d_in[1];
    const float* b1 = (const float*)d_in[2];
    const float* W2 = (const float*)d_in[3];
    const float* b2 = (const float*)d_in[4];
    const float* W3 = (const float*)d_in[5];
    const float* b3 = (const float*)d_in[6];
    float* out = (float*)d_out;

    const int smem_bytes = (TI * DD + TJ * DD + DCH * WPITCH + NPAIR * 151 + WPITCH)
                           * (int)sizeof(float);  // 190,560 B
    cudaFuncSetAttribute(k2_pairs, cudaFuncAttributeMaxDynamicSharedMemorySize,
                         smem_bytes);

    k1_precompute<<<BB * NN / 8, 160>>>(E, W1, b1);
    dim3 g2(NN / TI, NN / TJ, BB);
    k2_pairs<<<g2, 256, smem_bytes>>>(E, W1, W2, b2, W3, b3);
    k3_softmax<<<dim3(NN, BB), NN>>>(out);
}

// round 3
// speedup vs baseline: 10.9450x; 10.9450x over previous
#include <cuda_runtime.h>
#include <cuda_bf16.h>
#include <cstdint>

#define HH 150

// Padded pitches (u32 words) chosen so (pitch mod 32) = 4 or 20 -> conflict-free
#define EPITCH   388   // E row: 776 bf16 = 1552B
#define WABPITCH 36    // wab row: 72 bf16 = 144B (K=64 chunks)
#define W1CPITCH 68    // w1c row: 136 bf16 = 272B (K=128 chunks)
#define W2PITCH  84    // w2 row: 168 bf16 = 336B
#define H1PITCH  84

// ---------------- device scratch (allocation-free rule) ----------------
__device__ __align__(16) uint32_t      g_Ebf[1536 * EPITCH];      // bf16x2 E, padded rows
__device__ __align__(16) __nv_bfloat16 g_wabT[12 * 304 * 72];     // [chunk][n:304][k:72] n-major
__device__ __align__(16) __nv_bfloat16 g_w1cT[6 * 152 * 136];     // [chunk][n:152][k:136]
__device__ __align__(16) __nv_bfloat16 g_w2T[152 * 168];          // [n:152][k:168]
__device__ float g_A[1536 * HH];
__device__ float g_B[1536 * HH];
__device__ float g_S[8 * 192 * 192];

// ---------------- helpers ----------------
__device__ __forceinline__ uint32_t smem_u32(const void* p) {
    uint32_t a;
    asm("{ .reg .u64 t; cvta.to.shared.u64 t, %1; cvt.u32.u64 %0, t; }" : "=r"(a) : "l"(p));
    return a;
}
__device__ __forceinline__ uint32_t packbf(float lo, float hi) {
    uint32_t d; asm("cvt.rn.bf16x2.f32 %0, %1, %2;" : "=r"(d) : "f"(hi), "f"(lo)); return d;
}
__device__ __forceinline__ uint32_t bmul2(uint32_t a, uint32_t b) {
    uint32_t d; asm("mul.rn.bf16x2 %0, %1, %2;" : "=r"(d) : "r"(a), "r"(b)); return d;
}
__device__ __forceinline__ void mma16816(float* d, const uint32_t* a, const uint32_t* b,
                                         const float* c) {
    asm volatile(
        "mma.sync.aligned.m16n8k16.row.col.f32.bf16.bf16.f32 "
        "{%0,%1,%2,%3}, {%4,%5,%6,%7}, {%8,%9}, {%10,%11,%12,%13};"
        : "=f"(d[0]), "=f"(d[1]), "=f"(d[2]), "=f"(d[3])
        : "r"(a[0]), "r"(a[1]), "r"(a[2]), "r"(a[3]), "r"(b[0]), "r"(b[1]),
          "f"(c[0]), "f"(c[1]), "f"(c[2]), "f"(c[3]));
}
#define MBAR_INIT(mb, cnt) asm volatile("mbarrier.init.shared.b64 [%0], %1;" :: "r"((uint32_t)(mb)), "r"((uint32_t)(cnt)) : "memory")
#define MBAR_EXPECT_TX(mb, n) asm volatile("mbarrier.arrive.expect_tx.shared.b64 _, [%0], %1;" :: "r"((uint32_t)(mb)), "r"((uint32_t)(n)) : "memory")
#define FENCE_ASYNC() asm volatile("fence.proxy.async.shared::cta;" ::: "memory")
#define MBAR_WAIT(mb, ph) do { \
    uint32_t _m = (uint32_t)(mb); uint32_t _p = (uint32_t)(ph); uint32_t _d; \
    asm volatile("{\n\t.reg .pred p;\n\tmbarrier.try_wait.parity.acquire.cta.shared::cta.b64 p, [%1], %2;\n\tselp.b32 %0, 1, 0, p;\n\t}" \
        : "=r"(_d) : "r"(_m), "r"(_p) : "memory"); \
    if (!_d) { \
        asm volatile("{\n\t.reg .pred P1;\n\tWL_%=:\n\tmbarrier.try_wait.parity.acquire.cta.shared::cta.b64 P1, [%0], %1, 0x989680;\n\t@P1 bra.uni WD_%=;\n\tbra.uni WL_%=;\n\tWD_%=:\n\t}" \
            :: "r"(_m), "r"(_p) : "memory"); \
    } } while (0)
__device__ __forceinline__ void bulk_g2s(uint32_t dst, const void* src, uint32_t bytes, uint32_t mbar) {
    asm volatile("cp.async.bulk.shared::cta.global.mbarrier::complete_tx::bytes [%0], [%1], %2, [%3];"
        :: "r"(dst), "l"(src), "r"(bytes), "r"(mbar) : "memory");
}

// ---------------- prep: E fp32 -> bf16x2 padded rows ----------------
__global__ void kprep_e(const float* __restrict__ E) {
    int idx = blockIdx.x * 256 + threadIdx.x;
    if (idx >= 1536 * EPITCH) return;
    int r = idx / EPITCH, w = idx % EPITCH;
    int k0 = 2 * w;
    uint32_t v = 0;
    if (k0 < 768) {
        float2 e = *reinterpret_cast<const float2*>(E + (size_t)r * 768 + k0);
        v = packbf(e.x, e.y);
    }
    g_Ebf[idx] = v;
}

// ---------------- prep: weights -> n-major bf16 padded blobs ----------------
#define WAB_N (12 * 304 * 72)
#define W1C_N (6 * 152 * 136)
#define W2_N  (152 * 168)
__global__ void kprep_w(const float* __restrict__ W1, const float* __restrict__ W2) {
    int idx = blockIdx.x * 256 + threadIdx.x;
    if (idx < WAB_N) {
        int c = idx / (304 * 72), rem = idx % (304 * 72);
        int n = rem / 72, k = rem % 72;
        float v = 0.f;
        if (k < 64) {
            int kg = c * 64 + k;
            if (n < 152) { if (n < HH) v = W1[(size_t)kg * HH + n]; }
            else { int h = n - 152; if (h < HH) v = W1[(size_t)(768 + kg) * HH + h]; }
        }
        g_wabT[idx] = __float2bfloat16(v);
    } else if (idx < WAB_N + W1C_N) {
        int t = idx - WAB_N;
        int c = t / (152 * 136), rem = t % (152 * 136);
        int n = rem / 136, k = rem % 136;
        float v = 0.f;
        if (k < 128 && n < HH) v = W1[(size_t)(1536 + c * 128 + k) * HH + n];
        g_w1cT[t] = __float2bfloat16(v);
    } else if (idx < WAB_N + W1C_N + W2_N) {
        int t = idx - WAB_N - W1C_N;
        int n = t / 168, k = t % 168;
        float v = 0.f;
        if (n < HH && k < HH) v = W2[(size_t)k * HH + n];
        g_w2T[t] = __float2bfloat16(v);
    }
}

// ---------------- k1: seeds  [1536 x 768] @ [768 x 304] -> g_A, g_B ----------------
// 24 blocks x 256 thr. Warp w: wm=w&3 (m16 block of 64 rows), wn=w>>2 (N half of 152).
#define K1_SE_BYTES (64 * EPITCH * 4)
#define K1_W_BYTES  (304 * WABPITCH * 4)
#define K1_BAR_OFF  (K1_SE_BYTES + 2 * K1_W_BYTES)
#define K1_SMEM     (K1_BAR_OFF + 64)

__global__ __launch_bounds__(256, 1)
void k1_mma(const float* __restrict__ b1) {
    extern __shared__ __align__(128) char smem[];
    uint32_t* sE = (uint32_t*)smem;
    uint32_t* sW[2] = { (uint32_t*)(smem + K1_SE_BYTES),
                        (uint32_t*)(smem + K1_SE_BYTES + K1_W_BYTES) };
    const uint32_t barE = smem_u32(smem + K1_BAR_OFF);
    const uint32_t barW[2] = { barE + 8, barE + 16 };
    const int tid = threadIdx.x, w = tid >> 5, lane = tid & 31;
    const int wm = w & 3, wn = w >> 2;
    const int gq = lane >> 2, qq = lane & 3;
    const int r0 = blockIdx.x * 64;

    if (tid == 0) {
        MBAR_INIT(barE, 1); MBAR_INIT(barW[0], 1); MBAR_INIT(barW[1], 1);
        FENCE_ASYNC();
        MBAR_EXPECT_TX(barE, K1_SE_BYTES);
        bulk_g2s(smem_u32(sE), g_Ebf + (size_t)r0 * EPITCH, K1_SE_BYTES, barE);
        MBAR_EXPECT_TX(barW[0], K1_W_BYTES);
        bulk_g2s(smem_u32(sW[0]), g_wabT, K1_W_BYTES, barW[0]);
        MBAR_EXPECT_TX(barW[1], K1_W_BYTES);
        bulk_g2s(smem_u32(sW[1]), g_wabT + (size_t)304 * 72, K1_W_BYTES, barW[1]);
    }
    __syncthreads();
    MBAR_WAIT(barE, 0);

    float acc[19][4];
#pragma unroll
    for (int nb = 0; nb < 19; nb++)
#pragma unroll
        for (int u = 0; u < 4; u++) acc[nb][u] = 0.f;

    const uint32_t* Ea = sE + (size_t)(16 * wm + gq) * EPITCH;
    const uint32_t* Eb = Ea + 8 * EPITCH;

    for (int c = 0; c < 12; c++) {
        MBAR_WAIT(barW[c & 1], (c >> 1) & 1);
        const uint32_t* Wb = sW[c & 1];
        for (int ks = 0; ks < 4; ks++) {
            int kkw = c * 32 + ks * 8 + qq;
            uint32_t a[4] = { Ea[kkw], Eb[kkw], Ea[kkw + 4], Eb[kkw + 4] };
            int kks = ks * 8 + qq;
#pragma unroll
            for (int nb = 0; nb < 19; nb++) {
                int nrow = wn * 152 + nb * 8 + gq;
                uint32_t b[2] = { Wb[nrow * WABPITCH + kks], Wb[nrow * WABPITCH + kks + 4] };
                mma16816(acc[nb], a, b, acc[nb]);
            }
        }
        __syncthreads();
        if (tid == 0 && c + 2 < 12) {
            MBAR_EXPECT_TX(barW[c & 1], K1_W_BYTES);
            bulk_g2s(smem_u32(sW[c & 1]), g_wabT + (size_t)(c + 2) * 304 * 72,
                     K1_W_BYTES, barW[c & 1]);
        }
    }

    const int ra = r0 + 16 * wm + gq, rb = ra + 8;
#pragma unroll
    for (int nb = 0; nb < 19; nb++) {
        int nl0 = wn * 152 + nb * 8 + qq * 2;
#pragma unroll
        for (int u = 0; u < 4; u++) {
            int row = (u < 2) ? ra : rb;
            int nl = nl0 + (u & 1);
            float v = acc[nb][u];
            if (nl < 152) { if (nl < HH) g_A[(size_t)row * HH + nl] = v + __ldg(b1 + nl); }
            else { int h = nl - 152; if (h < HH) g_B[(size_t)row * HH + h] = v; }
        }
    }
}

// ---------------- k2: fused pair MLP ----------------
// grid (12,24,8), 256 thr. Warp w: rows 16w..16w+15 of the 128-pair tile, full N=152.
#define K2_EI_BYTES (16 * EPITCH * 4)
#define K2_EJ_BYTES (8 * EPITCH * 4)
#define K2_W_BYTES  (152 * W1CPITCH * 4)   // 41344
#define K2_W2_BYTES (152 * W2PITCH * 4)    // 51072 (spans both W buffers)
#define K2_EJ_OFF   K2_EI_BYTES
#define K2_W_OFF    (K2_EI_BYTES + K2_EJ_BYTES)
#define K2_H1_OFF   (K2_W_OFF + 2 * K2_W_BYTES)
#define K2_BAR_OFF  (K2_H1_OFF + 128 * H1PITCH * 4)
#define K2_SMEM     (K2_BAR_OFF + 64)

__global__ __launch_bounds__(256, 1)
void k2_mma(const float* __restrict__ b2,
            const float* __restrict__ W3,
            const float* __restrict__ b3) {
    const int ti = blockIdx.x, tj = blockIdx.y, bz = blockIdx.z;
    if (tj * 8 >= ti * 16 + 15) return;

    extern __shared__ __align__(128) char smem[];
    uint32_t* sEi = (uint32_t*)smem;
    uint32_t* sEj = (uint32_t*)(smem + K2_EJ_OFF);
    uint32_t* sW[2] = { (uint32_t*)(smem + K2_W_OFF),
                        (uint32_t*)(smem + K2_W_OFF + K2_W_BYTES) };
    uint32_t* sH1 = (uint32_t*)(smem + K2_H1_OFF);
    const uint32_t barE = smem_u32(smem + K2_BAR_OFF);
    const uint32_t barW[2] = { barE + 8, barE + 16 };
    const int tid = threadIdx.x, w = tid >> 5, lane = tid & 31;
    const int gq = lane >> 2, qq = lane & 3;

    if (tid == 0) {
        MBAR_INIT(barE, 1); MBAR_INIT(barW[0], 1); MBAR_INIT(barW[1], 1);
        FENCE_ASYNC();
        MBAR_EXPECT_TX(barE, K2_EI_BYTES + K2_EJ_BYTES);
        bulk_g2s(smem_u32(sEi), g_Ebf + ((size_t)bz * 192 + ti * 16) * EPITCH, K2_EI_BYTES, barE);
        bulk_g2s(smem_u32(sEj), g_Ebf + ((size_t)bz * 192 + tj * 8) * EPITCH, K2_EJ_BYTES, barE);
        MBAR_EXPECT_TX(barW[0], K2_W_BYTES);
        bulk_g2s(smem_u32(sW[0]), g_w1cT, K2_W_BYTES, barW[0]);
        MBAR_EXPECT_TX(barW[1], K2_W_BYTES);
        bulk_g2s(smem_u32(sW[1]), g_w1cT + (size_t)152 * 136, K2_W_BYTES, barW[1]);
    }
    // zero h1s pad words 76..79 (read by layer-2 K padding)
    for (int idx = tid; idx < 128 * 4; idx += 256)
        sH1[(idx >> 2) * H1PITCH + 76 + (idx & 3)] = 0;
    __syncthreads();
    MBAR_WAIT(barE, 0);

    float acc[19][4];
#pragma unroll
    for (int nb = 0; nb < 19; nb++)
#pragma unroll
        for (int u = 0; u < 4; u++) acc[nb][u] = 0.f;

    const uint32_t* Ei0 = sEi + (size_t)(2 * w) * EPITCH;
    const uint32_t* Ei1 = Ei0 + EPITCH;
    const uint32_t* Ejp = sEj + (size_t)gq * EPITCH;

    // ---- layer 1: 6 K-chunks of 128 ----
    for (int c = 0; c < 6; c++) {
        MBAR_WAIT(barW[c & 1], (c >> 1) & 1);
        const uint32_t* Wb = sW[c & 1];
        for (int ks = 0; ks < 8; ks++) {
            int kkw = c * 64 + ks * 8 + qq;
            uint32_t a[4] = { bmul2(Ei0[kkw], Ejp[kkw]),
                              bmul2(Ei1[kkw], Ejp[kkw]),
                              bmul2(Ei0[kkw + 4], Ejp[kkw + 4]),
                              bmul2(Ei1[kkw + 4], Ejp[kkw + 4]) };
            int kks = ks * 8 + qq;
#pragma unroll
            for (int nb = 0; nb < 19; nb++) {
                int nrow = nb * 8 + gq;
                uint32_t b[2] = { Wb[nrow * W1CPITCH + kks], Wb[nrow * W1CPITCH + kks + 4] };
                mma16816(acc[nb], a, b, acc[nb]);
            }
        }
        __syncthreads();
        if (tid == 0 && c + 2 < 6) {
            MBAR_EXPECT_TX(barW[c & 1], K2_W_BYTES);
            bulk_g2s(smem_u32(sW[c & 1]), g_w1cT + (size_t)(c + 2) * 152 * 136,
                     K2_W_BYTES, barW[c & 1]);
        }
    }
    // both W buffers free -> prefetch W2 (spans both), overlaps epilogue 1
    if (tid == 0) {
        MBAR_EXPECT_TX(barW[0], K2_W2_BYTES);
        bulk_g2s(smem_u32(sW[0]), g_w2T, K2_W2_BYTES, barW[0]);
    }

    // ---- epilogue 1: + seeds, ReLU, bf16 -> sH1 ----
    const int pa = 16 * w + gq, pb = pa + 8;
    const int ia = ti * 16 + (pa >> 3), ja = tj * 8 + (pa & 7);
    const int ib = ti * 16 + (pb >> 3), jb = tj * 8 + (pb & 7);
    const float* Aa = g_A + ((size_t)bz * 192 + ia) * HH;
    const float* Ba = g_B + ((size_t)bz * 192 + ja) * HH;
    const float* Ab = g_A + ((size_t)bz * 192 + ib) * HH;
    const float* Bb = g_B + ((size_t)bz * 192 + jb) * HH;
#pragma unroll
    for (int nb = 0; nb < 19; nb++) {
        int h = nb * 8 + qq * 2;
        float s0a = 0.f, s1a = 0.f, s0b = 0.f, s1b = 0.f;
        if (h < HH) {  // h even; h<150 implies h+1<=149
            float2 va = *reinterpret_cast<const float2*>(Aa + h);
            float2 wa = *reinterpret_cast<const float2*>(Ba + h);
            float2 vb = *reinterpret_cast<const float2*>(Ab + h);
            float2 wb = *reinterpret_cast<const float2*>(Bb + h);
            s0a = va.x + wa.x; s1a = va.y + wa.y;
            s0b = vb.x + wb.x; s1b = vb.y + wb.y;
        }
        float v0 = fmaxf(acc[nb][0] + s0a, 0.f), v1 = fmaxf(acc[nb][1] + s1a, 0.f);
        float v2 = fmaxf(acc[nb][2] + s0b, 0.f), v3 = fmaxf(acc[nb][3] + s1b, 0.f);
        sH1[pa * H1PITCH + nb * 4 + qq] = packbf(v0, v1);
        sH1[pb * H1PITCH + nb * 4 + qq] = packbf(v2, v3);
    }
    __syncthreads();
    MBAR_WAIT(barW[0], 1);   // W2 ready (4th completion on barW0? no: 0:c0,1:c2,0:c4 -> next parity 1)

    // ---- layer 2: K=160 (10 k16 steps), A from sH1, B = W2 ----
#pragma unroll
    for (int nb = 0; nb < 19; nb++)
#pragma unroll
        for (int u = 0; u < 4; u++) acc[nb][u] = 0.f;
    const uint32_t* W2b = sW[0];
    const uint32_t* Ha = sH1 + pa * H1PITCH;
    const uint32_t* Hb = sH1 + pb * H1PITCH;
    for (int ks = 0; ks < 10; ks++) {
        int kks = ks * 8 + qq;
        uint32_t a[4] = { Ha[kks], Hb[kks], Ha[kks + 4], Hb[kks + 4] };
#pragma unroll
        for (int nb = 0; nb < 19; nb++) {
            int nrow = nb * 8 + gq;
            uint32_t b[2] = { W2b[nrow * W2PITCH + kks], W2b[nrow * W2PITCH + kks + 4] };
            mma16816(acc[nb], a, b, acc[nb]);
        }
    }

    // ---- epilogue 2: +b2, ReLU, dot W3, quad-reduce, store scores ----
    float spa = 0.f, spb = 0.f;
#pragma unroll
    for (int nb = 0; nb < 19; nb++) {
        int h0 = nb * 8 + qq * 2, h1 = h0 + 1;
        if (h0 < HH) {
            float bb = __ldg(b2 + h0), ww = __ldg(W3 + h0);
            spa += fmaxf(acc[nb][0] + bb, 0.f) * ww;
            spb += fmaxf(acc[nb][2] + bb, 0.f) * ww;
        }
        if (h1 < HH) {
            float bb = __ldg(b2 + h1), ww = __ldg(W3 + h1);
            spa += fmaxf(acc[nb][1] + bb, 0.f) * ww;
            spb += fmaxf(acc[nb][3] + bb, 0.f) * ww;
        }
    }
    spa += __shfl_xor_sync(0xffffffffu, spa, 1);
    spa += __shfl_xor_sync(0xffffffffu, spa, 2);
    spb += __shfl_xor_sync(0xffffffffu, spb, 1);
    spb += __shfl_xor_sync(0xffffffffu, spb, 2);
    if (qq == 0) {
        float bias = __ldg(b3);
        if (ja < ia) g_S[((size_t)bz * 192 + ia) * 192 + ja] = spa + bias;
        if (jb < ib) g_S[((size_t)bz * 192 + ib) * 192 + jb] = spb + bias;
    }
}

// ---------------- k3: tril softmax ----------------
__global__ void k3_softmax(float* __restrict__ out) {
    const int i = blockIdx.x, b = blockIdx.y, j = threadIdx.x;
    float val;
    if (j < i)       val = g_S[((size_t)b * 192 + i) * 192 + j];
    else if (j == i) val = 0.f;
    else             val = -1e30f;

    __shared__ float red[6];
    float m = val;
#pragma unroll
    for (int o = 16; o; o >>= 1) m = fmaxf(m, __shfl_xor_sync(0xffffffffu, m, o));
    if ((j & 31) == 0) red[j >> 5] = m;
    __syncthreads();
    float M = fmaxf(fmaxf(fmaxf(red[0], red[1]), fmaxf(red[2], red[3])), fmaxf(red[4], red[5]));
    __syncthreads();
    float e = (j <= i) ? expf(val - M) : 0.f;
    float s = e;
#pragma unroll
    for (int o = 16; o; o >>= 1) s += __shfl_xor_sync(0xffffffffu, s, o);
    if ((j & 31) == 0) red[j >> 5] = s;
    __syncthreads();
    float S = red[0] + red[1] + red[2] + red[3] + red[4] + red[5];
    out[((size_t)b * 192 + i) * 192 + j] = (j <= i) ? (e / S) : -1000.0f;
}

// ---------------------------------------------------------------------------
extern "C" void kernel_launch(void* const* d_in, const int* in_sizes, int n_in,
                              void* d_out, int out_size) {
    const float* E  = (const float*)d_in[0];
    const float* W1 = (const float*)d_in[1];
    const float* b1 = (const float*)d_in[2];
    const float* W2 = (const float*)d_in[3];
    const float* b2 = (const float*)d_in[4];
    const float* W3 = (const float*)d_in[5];
    const float* b3 = (const float*)d_in[6];
    float* out = (float*)d_out;

    cudaFuncSetAttribute(k1_mma, cudaFuncAttributeMaxDynamicSharedMemorySize, K1_SMEM);
    cudaFuncSetAttribute(k2_mma, cudaFuncAttributeMaxDynamicSharedMemorySize, K2_SMEM);

    kprep_e<<<(1536 * EPITCH + 255) / 256, 256>>>(E);
    kprep_w<<<(WAB_N + W1C_N + W2_N + 255) / 256, 256>>>(W1, W2);
    k1_mma<<<24, 256, K1_SMEM>>>(b1);
    k2_mma<<<dim3(12, 24, 8), 256, K2_SMEM>>>(b2, W3, b3);
    k3_softmax<<<dim3(192, 8), 192>>>(out);
}

// round 4
// speedup vs baseline: 12.1059x; 1.1061x over previous
#include <cuda_runtime.h>
#include <cuda_bf16.h>
#include <cstdint>

#define HH 150

#define EPITCH 392          // E row pitch in u32 words (768 bf16 = 384 words + 8 pad; %32==8)
#define H1PITCH 88          // h1 row pitch in u32 words (%32==24)
#define WABPITCH 36         // k1 weight row pitch (u32 words)

// Packed-fragment W blob geometry (k2): per k16-step: 32 lanes * 44 words
#define PKS 1408            // words per k-step slab
#define W1C_CHUNK_W 11264   // 8 ks * 1408 (K=128 chunk)
#define W2_W 14080          // 10 ks * 1408 (K=160)

// ---------------- device scratch ----------------
__device__ __align__(16) uint32_t      g_Ebf[1536 * EPITCH];        // interleaved bf16x2 E
__device__ __align__(16) __nv_bfloat16 g_wabT[12 * 320 * 72];       // k1 W[a|b], n-major
__device__ __align__(16) uint32_t      g_w1cP[6 * W1C_CHUNK_W];     // k2 W1c packed frags
__device__ __align__(16) uint32_t      g_w2P[W2_W];                 // k2 W2 packed frags
__device__ float g_A[1536 * HH];
__device__ float g_B[1536 * HH];
__device__ float g_S[8 * 192 * 192];

// ---------------- helpers ----------------
__device__ __forceinline__ uint32_t smem_u32(const void* p) {
    uint32_t a;
    asm("{ .reg .u64 t; cvta.to.shared.u64 t, %1; cvt.u32.u64 %0, t; }" : "=r"(a) : "l"(p));
    return a;
}
__device__ __forceinline__ uint32_t packbf(float lo, float hi) {
    uint32_t d; asm("cvt.rn.bf16x2.f32 %0, %1, %2;" : "=r"(d) : "f"(hi), "f"(lo)); return d;
}
__device__ __forceinline__ uint32_t bmul2(uint32_t a, uint32_t b) {
    uint32_t d; asm("mul.rn.bf16x2 %0, %1, %2;" : "=r"(d) : "r"(a), "r"(b)); return d;
}
__device__ __forceinline__ void mma16816(float* d, const uint32_t* a, const uint32_t* b,
                                         const float* c) {
    asm volatile(
        "mma.sync.aligned.m16n8k16.row.col.f32.bf16.bf16.f32 "
        "{%0,%1,%2,%3}, {%4,%5,%6,%7}, {%8,%9}, {%10,%11,%12,%13};"
        : "=f"(d[0]), "=f"(d[1]), "=f"(d[2]), "=f"(d[3])
        : "r"(a[0]), "r"(a[1]), "r"(a[2]), "r"(a[3]), "r"(b[0]), "r"(b[1]),
          "f"(c[0]), "f"(c[1]), "f"(c[2]), "f"(c[3]));
}
#define MBAR_INIT(mb, cnt) asm volatile("mbarrier.init.shared.b64 [%0], %1;" :: "r"((uint32_t)(mb)), "r"((uint32_t)(cnt)) : "memory")
#define MBAR_EXPECT_TX(mb, n) asm volatile("mbarrier.arrive.expect_tx.shared.b64 _, [%0], %1;" :: "r"((uint32_t)(mb)), "r"((uint32_t)(n)) : "memory")
#define FENCE_ASYNC() asm volatile("fence.proxy.async.shared::cta;" ::: "memory")
#define MBAR_WAIT(mb, ph) do { \
    uint32_t _m = (uint32_t)(mb); uint32_t _p = (uint32_t)(ph); uint32_t _d; \
    asm volatile("{\n\t.reg .pred p;\n\tmbarrier.try_wait.parity.acquire.cta.shared::cta.b64 p, [%1], %2;\n\tselp.b32 %0, 1, 0, p;\n\t}" \
        : "=r"(_d) : "r"(_m), "r"(_p) : "memory"); \
    if (!_d) { \
        asm volatile("{\n\t.reg .pred P1;\n\tWL_%=:\n\tmbarrier.try_wait.parity.acquire.cta.shared::cta.b64 P1, [%0], %1, 0x989680;\n\t@P1 bra.uni WD_%=;\n\tbra.uni WL_%=;\n\tWD_%=:\n\t}" \
            :: "r"(_m), "r"(_p) : "memory"); \
    } } while (0)
__device__ __forceinline__ void bulk_g2s(uint32_t dst, const void* src, uint32_t bytes, uint32_t mbar) {
    asm volatile("cp.async.bulk.shared::cta.global.mbarrier::complete_tx::bytes [%0], [%1], %2, [%3];"
        :: "r"(dst), "l"(src), "r"(bytes), "r"(mbar) : "memory");
}

// ---------------- prep: E -> interleaved bf16x2 ----------------
// word position p in each 8-word k16 group encodes (q,h): p = 2q+h, source kword = g*8+q+4h.
__global__ void kprep_e(const float* __restrict__ E) {
    int idx = blockIdx.x * 256 + threadIdx.x;
    if (idx >= 1536 * EPITCH) return;
    int r = idx / EPITCH, pos = idx % EPITCH;
    int g = pos >> 3, wi = pos & 7, q = wi >> 1, h = wi & 1;
    int kw = g * 8 + q + 4 * h;
    uint32_t v = 0;
    if (kw < 384) {
        float2 e = *reinterpret_cast<const float2*>(E + (size_t)r * 768 + 2 * kw);
        v = packbf(e.x, e.y);
    }
    g_Ebf[idx] = v;
}

// ---------------- prep: weights ----------------
#define WAB_N (12 * 320 * 72)
#define W1CP_N (6 * W1C_CHUNK_W)
__global__ void kprep_w(const float* __restrict__ W1, const float* __restrict__ W2) {
    int idx = blockIdx.x * 256 + threadIdx.x;
    if (idx < WAB_N) {
        int c = idx / (320 * 72), rem = idx % (320 * 72);
        int n = rem / 72, kk = rem % 72;
        float v = 0.f;
        if (kk < 64) {
            int kg = c * 64 + kk;
            if (n < 160) { if (n < HH) v = W1[(size_t)kg * HH + n]; }
            else { int h = n - 160; if (h < HH) v = W1[(size_t)(768 + kg) * HH + h]; }
        }
        g_wabT[idx] = __float2bfloat16(v);
    } else if (idx < WAB_N + W1CP_N + W2_W) {
        int t = idx - WAB_N;
        bool isW2 = (t >= W1CP_N);
        int c = 0, r;
        if (isW2) r = t - W1CP_N;
        else { c = t / W1C_CHUNK_W; r = t % W1C_CHUNK_W; }
        int ks = r / PKS, r1 = r % PKS;
        int lane = r1 / 44, r2 = r1 % 44;
        uint32_t v = 0;
        if (r2 < 40) {
            int nh = r2 / 20, r3 = r2 % 20, m = r3 / 4, e = r3 % 4;
            int gq = lane >> 2, qq = lane & 3;
            int nb = nh * 10 + 2 * m + (e >> 1);
            int kwl = ks * 8 + qq + (e & 1) * 4;
            int n = nb * 8 + gq;
            float v0 = 0.f, v1 = 0.f;
            if (n < HH) {
                if (isW2) {
                    int k0 = 2 * kwl;
                    if (k0 < HH)     v0 = W2[(size_t)k0 * HH + n];
                    if (k0 + 1 < HH) v1 = W2[(size_t)(k0 + 1) * HH + n];
                } else {
                    int k0 = c * 128 + 2 * kwl;   // < 768 always
                    v0 = W1[(size_t)(1536 + k0) * HH + n];
                    v1 = W1[(size_t)(1536 + k0 + 1) * HH + n];
                }
            }
            v = packbf(v0, v1);
        }
        if (isW2) g_w2P[r] = v; else g_w1cP[(size_t)c * W1C_CHUNK_W + r] = v;
    }
}

// ---------------- k1: seeds GEMM [1536x768]@[768x320] -> g_A,g_B ----------------
// 48 blocks x 32 rows. 8 warps: each m32 (all rows) x n40 (5 n-blocks).
#define K1_E_BYTES (32 * EPITCH * 4)            // 50176
#define K1_W_BYTES (320 * WABPITCH * 4)         // 46080
#define K1_BAR_OFF (K1_E_BYTES + 2 * K1_W_BYTES)
#define K1_SMEM    (K1_BAR_OFF + 64)

__global__ __launch_bounds__(256, 1)
void k1_mma(const float* __restrict__ b1) {
    extern __shared__ __align__(128) char smem[];
    uint32_t* sE = (uint32_t*)smem;
    uint32_t* sW[2] = { (uint32_t*)(smem + K1_E_BYTES),
                        (uint32_t*)(smem + K1_E_BYTES + K1_W_BYTES) };
    const uint32_t barE = smem_u32(smem + K1_BAR_OFF);
    const uint32_t barW[2] = { barE + 8, barE + 16 };
    const int tid = threadIdx.x, w = tid >> 5, lane = tid & 31;
    const int gq = lane >> 2, qq = lane & 3;
    const int r0 = blockIdx.x * 32;

    if (tid == 0) {
        MBAR_INIT(barE, 1); MBAR_INIT(barW[0], 1); MBAR_INIT(barW[1], 1);
        FENCE_ASYNC();
        MBAR_EXPECT_TX(barE, K1_E_BYTES);
        bulk_g2s(smem_u32(sE), g_Ebf + (size_t)r0 * EPITCH, K1_E_BYTES, barE);
        MBAR_EXPECT_TX(barW[0], K1_W_BYTES);
        bulk_g2s(smem_u32(sW[0]), g_wabT, K1_W_BYTES, barW[0]);
        MBAR_EXPECT_TX(barW[1], K1_W_BYTES);
        bulk_g2s(smem_u32(sW[1]), g_wabT + (size_t)320 * 72, K1_W_BYTES, barW[1]);
    }
    __syncthreads();
    MBAR_WAIT(barE, 0);

    float acc[2][5][4];
#pragma unroll
    for (int t = 0; t < 2; t++)
#pragma unroll
        for (int l = 0; l < 5; l++)
#pragma unroll
            for (int u = 0; u < 4; u++) acc[t][l][u] = 0.f;

    const uint32_t* e0p = sE + (size_t)gq * EPITCH;
    const uint32_t* e1p = e0p + 8 * EPITCH;
    const uint32_t* e2p = e0p + 16 * EPITCH;
    const uint32_t* e3p = e0p + 24 * EPITCH;

    for (int c = 0; c < 12; c++) {
        MBAR_WAIT(barW[c & 1], (c >> 1) & 1);
        const uint32_t* Wb = sW[c & 1];
#pragma unroll
        for (int ks = 0; ks < 4; ks++) {
            int kb = c * 32 + ks * 8 + 2 * qq;
            uint2 e0 = *(const uint2*)(e0p + kb);
            uint2 e1 = *(const uint2*)(e1p + kb);
            uint2 e2 = *(const uint2*)(e2p + kb);
            uint2 e3 = *(const uint2*)(e3p + kb);
            uint32_t a0[4] = { e0.x, e1.x, e0.y, e1.y };
            uint32_t a1[4] = { e2.x, e3.x, e2.y, e3.y };
#pragma unroll
            for (int l = 0; l < 5; l++) {
                int nrow = (w * 5 + l) * 8 + gq;
                uint32_t b[2] = { Wb[nrow * WABPITCH + ks * 8 + qq],
                                  Wb[nrow * WABPITCH + ks * 8 + qq + 4] };
                mma16816(acc[0][l], a0, b, acc[0][l]);
                mma16816(acc[1][l], a1, b, acc[1][l]);
            }
        }
        __syncthreads();
        if (tid == 0 && c + 2 < 12) {
            MBAR_EXPECT_TX(barW[c & 1], K1_W_BYTES);
            bulk_g2s(smem_u32(sW[c & 1]), g_wabT + (size_t)(c + 2) * 320 * 72,
                     K1_W_BYTES, barW[c & 1]);
        }
    }

#pragma unroll
    for (int t = 0; t < 2; t++)
#pragma unroll
        for (int l = 0; l < 5; l++) {
            int n0 = (w * 5 + l) * 8 + 2 * qq;
            int ra = r0 + 16 * t + gq, rb = ra + 8;
#pragma unroll
            for (int u = 0; u < 4; u++) {
                int row = (u < 2) ? ra : rb;
                int n = n0 + (u & 1);
                float v = acc[t][l][u];
                if (n < 160) { if (n < HH) g_A[(size_t)row * HH + n] = v + __ldg(b1 + n); }
                else { int h = n - 160; if (h < HH) g_B[(size_t)row * HH + h] = v; }
            }
        }
}

// ---------------- k2: fused pair MLP ----------------
// grid (12,24,8), 256 thr. Warp w: mh=w>>1 (m32 rows), nh=w&1 (n80 half, N pad 160).
#define K2_EI_OFF  0
#define K2_EJ_OFF  (16 * EPITCH * 4)                    // 25088
#define K2_W_OFF   (K2_EJ_OFF + 8 * EPITCH * 4)         // 37632
#define K2_W2_OFF  (K2_W_OFF + 2 * W1C_CHUNK_W * 4)     // 127744
#define K2_H1_OFF  (K2_W2_OFF + W2_W * 4)               // 184064
#define K2_SC_OFF  (K2_H1_OFF + 128 * H1PITCH * 4)      // 229120
#define K2_BAR_OFF (K2_SC_OFF + 512)                    // 229632
#define K2_SMEM    (K2_BAR_OFF + 64)                    // 229696

__global__ __launch_bounds__(256, 1)
void k2_mma(const float* __restrict__ b2,
            const float* __restrict__ W3,
            const float* __restrict__ b3) {
    const int ti = blockIdx.x, tj = blockIdx.y, bz = blockIdx.z;
    if (tj * 8 >= ti * 16 + 15) return;

    extern __shared__ __align__(128) char smem[];
    uint32_t* sEi = (uint32_t*)(smem + K2_EI_OFF);
    uint32_t* sEj = (uint32_t*)(smem + K2_EJ_OFF);
    uint32_t* sW[2] = { (uint32_t*)(smem + K2_W_OFF),
                        (uint32_t*)(smem + K2_W_OFF + W1C_CHUNK_W * 4) };
    uint32_t* sW2 = (uint32_t*)(smem + K2_W2_OFF);
    uint32_t* sH1 = (uint32_t*)(smem + K2_H1_OFF);
    float*    sSc = (float*)(smem + K2_SC_OFF);
    const uint32_t barE = smem_u32(smem + K2_BAR_OFF);
    const uint32_t barW[2] = { barE + 8, barE + 16 };
    const uint32_t barW2 = barE + 24;
    const int tid = threadIdx.x, w = tid >> 5, lane = tid & 31;
    const int mh = w >> 1, nh = w & 1;
    const int gq = lane >> 2, qq = lane & 3;

    if (tid == 0) {
        MBAR_INIT(barE, 1); MBAR_INIT(barW[0], 1); MBAR_INIT(barW[1], 1); MBAR_INIT(barW2, 1);
        FENCE_ASYNC();
        MBAR_EXPECT_TX(barE, (16 + 8) * EPITCH * 4);
        bulk_g2s(smem_u32(sEi), g_Ebf + ((size_t)bz * 192 + ti * 16) * EPITCH, 16 * EPITCH * 4, barE);
        bulk_g2s(smem_u32(sEj), g_Ebf + ((size_t)bz * 192 + tj * 8) * EPITCH, 8 * EPITCH * 4, barE);
        MBAR_EXPECT_TX(barW2, W2_W * 4);
        bulk_g2s(smem_u32(sW2), g_w2P, W2_W * 4, barW2);
        MBAR_EXPECT_TX(barW[0], W1C_CHUNK_W * 4);
        bulk_g2s(smem_u32(sW[0]), g_w1cP, W1C_CHUNK_W * 4, barW[0]);
        MBAR_EXPECT_TX(barW[1], W1C_CHUNK_W * 4);
        bulk_g2s(smem_u32(sW[1]), g_w1cP + W1C_CHUNK_W, W1C_CHUNK_W * 4, barW[1]);
    }
    __syncthreads();
    MBAR_WAIT(barE, 0);

    float acc[2][10][4];
#pragma unroll
    for (int t = 0; t < 2; t++)
#pragma unroll
        for (int l = 0; l < 10; l++)
#pragma unroll
            for (int u = 0; u < 4; u++) acc[t][l][u] = 0.f;

    const uint32_t* eI0 = sEi + (size_t)(4 * mh + 0) * EPITCH;
    const uint32_t* eI1 = sEi + (size_t)(4 * mh + 1) * EPITCH;
    const uint32_t* eI2 = sEi + (size_t)(4 * mh + 2) * EPITCH;
    const uint32_t* eI3 = sEi + (size_t)(4 * mh + 3) * EPITCH;
    const uint32_t* eJp = sEj + (size_t)gq * EPITCH;
    const int bw_off = lane * 44 + nh * 20;

    // ---- layer 1: 6 K-chunks of 128 ----
    for (int c = 0; c < 6; c++) {
        MBAR_WAIT(barW[c & 1], (c >> 1) & 1);
        const uint32_t* Wb = sW[c & 1];
#pragma unroll 4
        for (int ks = 0; ks < 8; ks++) {
            int kb = c * 64 + ks * 8 + 2 * qq;
            uint2 ej = *(const uint2*)(eJp + kb);
            uint2 e0 = *(const uint2*)(eI0 + kb);
            uint2 e1 = *(const uint2*)(eI1 + kb);
            uint2 e2 = *(const uint2*)(eI2 + kb);
            uint2 e3 = *(const uint2*)(eI3 + kb);
            uint32_t a0[4] = { bmul2(e0.x, ej.x), bmul2(e1.x, ej.x),
                               bmul2(e0.y, ej.y), bmul2(e1.y, ej.y) };
            uint32_t a1[4] = { bmul2(e2.x, ej.x), bmul2(e3.x, ej.x),
                               bmul2(e2.y, ej.y), bmul2(e3.y, ej.y) };
            const uint32_t* bp = Wb + ks * PKS + bw_off;
#pragma unroll
            for (int m = 0; m < 5; m++) {
                uint4 bb = *(const uint4*)(bp + m * 4);
                uint32_t b0[2] = { bb.x, bb.y };
                uint32_t b1r[2] = { bb.z, bb.w };
                mma16816(acc[0][2 * m],     a0, b0,  acc[0][2 * m]);
                mma16816(acc[1][2 * m],     a1, b0,  acc[1][2 * m]);
                mma16816(acc[0][2 * m + 1], a0, b1r, acc[0][2 * m + 1]);
                mma16816(acc[1][2 * m + 1], a1, b1r, acc[1][2 * m + 1]);
            }
        }
        __syncthreads();
        if (tid == 0 && c + 2 < 6) {
            MBAR_EXPECT_TX(barW[c & 1], W1C_CHUNK_W * 4);
            bulk_g2s(smem_u32(sW[c & 1]), g_w1cP + (size_t)(c + 2) * W1C_CHUNK_W,
                     W1C_CHUNK_W * 4, barW[c & 1]);
        }
    }

    // ---- epilogue 1: + seeds, ReLU, bf16 -> sH1 (interleaved k-layout) ----
    const float* Ap[2][2];
    const float* Bp[2][2];
#pragma unroll
    for (int t = 0; t < 2; t++)
#pragma unroll
        for (int s = 0; s < 2; s++) {
            int r = 32 * mh + 16 * t + 8 * s + gq;
            int ip = ti * 16 + (r >> 3), jp = tj * 8 + (r & 7);
            Ap[t][s] = g_A + ((size_t)bz * 192 + ip) * HH;
            Bp[t][s] = g_B + ((size_t)bz * 192 + jp) * HH;
        }
#pragma unroll
    for (int t = 0; t < 2; t++)
#pragma unroll
        for (int l = 0; l < 10; l++) {
            int nbg = nh * 10 + l;
            int h0 = nbg * 8 + 2 * qq;
            float v0 = 0.f, v1 = 0.f, v2 = 0.f, v3 = 0.f;
            if (h0 < HH) {
                float2 sa0 = *(const float2*)(Ap[t][0] + h0);
                float2 sb0 = *(const float2*)(Bp[t][0] + h0);
                float2 sa1 = *(const float2*)(Ap[t][1] + h0);
                float2 sb1 = *(const float2*)(Bp[t][1] + h0);
                v0 = fmaxf(acc[t][l][0] + sa0.x + sb0.x, 0.f);
                v1 = fmaxf(acc[t][l][1] + sa0.y + sb0.y, 0.f);
                v2 = fmaxf(acc[t][l][2] + sa1.x + sb1.x, 0.f);
                v3 = fmaxf(acc[t][l][3] + sa1.y + sb1.y, 0.f);
            }
            int kw = nbg * 4 + qq;
            int ilvw = ((kw >> 3) << 3) + 2 * (kw & 3) + ((kw >> 2) & 1);
            sH1[(32 * mh + 16 * t + gq) * H1PITCH + ilvw]     = packbf(v0, v1);
            sH1[(32 * mh + 16 * t + 8 + gq) * H1PITCH + ilvw] = packbf(v2, v3);
        }
    __syncthreads();
    MBAR_WAIT(barW2, 0);

    // ---- layer 2: K=160 (10 k16 steps) ----
    float ac2[2][10][4];
#pragma unroll
    for (int t = 0; t < 2; t++)
#pragma unroll
        for (int l = 0; l < 10; l++)
#pragma unroll
            for (int u = 0; u < 4; u++) ac2[t][l][u] = 0.f;

    const uint32_t* h0p = sH1 + (size_t)(32 * mh + gq) * H1PITCH;
    const uint32_t* h1p = h0p + 8 * H1PITCH;
    const uint32_t* h2p = h0p + 16 * H1PITCH;
    const uint32_t* h3p = h0p + 24 * H1PITCH;
#pragma unroll 2
    for (int ks = 0; ks < 10; ks++) {
        int kb = ks * 8 + 2 * qq;
        uint2 x0 = *(const uint2*)(h0p + kb);
        uint2 x1 = *(const uint2*)(h1p + kb);
        uint2 x2 = *(const uint2*)(h2p + kb);
        uint2 x3 = *(const uint2*)(h3p + kb);
        uint32_t a0[4] = { x0.x, x1.x, x0.y, x1.y };
        uint32_t a1[4] = { x2.x, x3.x, x2.y, x3.y };
        const uint32_t* bp = sW2 + ks * PKS + bw_off;
#pragma unroll
        for (int m = 0; m < 5; m++) {
            uint4 bb = *(const uint4*)(bp + m * 4);
            uint32_t b0[2] = { bb.x, bb.y };
            uint32_t b1r[2] = { bb.z, bb.w };
            mma16816(ac2[0][2 * m],     a0, b0,  ac2[0][2 * m]);
            mma16816(ac2[1][2 * m],     a1, b0,  ac2[1][2 * m]);
            mma16816(ac2[0][2 * m + 1], a0, b1r, ac2[0][2 * m + 1]);
            mma16816(ac2[1][2 * m + 1], a1, b1r, ac2[1][2 * m + 1]);
        }
    }

    // ---- epilogue 2: +b2, ReLU, dot W3; cross-warp (nh) partial sum via smem ----
    float sp[2][2] = { {0.f, 0.f}, {0.f, 0.f} };
#pragma unroll
    for (int t = 0; t < 2; t++)
#pragma unroll
        for (int l = 0; l < 10; l++) {
            int h0 = (nh * 10 + l) * 8 + 2 * qq;
            if (h0 < HH) {
                float2 bv = *(const float2*)(b2 + h0);
                float2 wv = *(const float2*)(W3 + h0);
                sp[t][0] += fmaxf(ac2[t][l][0] + bv.x, 0.f) * wv.x
                          + fmaxf(ac2[t][l][1] + bv.y, 0.f) * wv.y;
                sp[t][1] += fmaxf(ac2[t][l][2] + bv.x, 0.f) * wv.x
                          + fmaxf(ac2[t][l][3] + bv.y, 0.f) * wv.y;
            }
        }
#pragma unroll
    for (int t = 0; t < 2; t++)
#pragma unroll
        for (int s = 0; s < 2; s++) {
            sp[t][s] += __shfl_xor_sync(0xffffffffu, sp[t][s], 1);
            sp[t][s] += __shfl_xor_sync(0xffffffffu, sp[t][s], 2);
        }
    if (nh == 0 && qq == 0) {
#pragma unroll
        for (int t = 0; t < 2; t++)
#pragma unroll
            for (int s = 0; s < 2; s++)
                sSc[32 * mh + 16 * t + 8 * s + gq] = sp[t][s];
    }
    __syncthreads();
    if (nh == 1 && qq == 0) {
        float b3v = __ldg(b3);
#pragma unroll
        for (int t = 0; t < 2; t++)
#pragma unroll
            for (int s = 0; s < 2; s++) {
                int r = 32 * mh + 16 * t + 8 * s + gq;
                int ip = ti * 16 + (r >> 3), jp = tj * 8 + (r & 7);
                if (jp < ip)
                    g_S[((size_t)bz * 192 + ip) * 192 + jp] = sp[t][s] + sSc[r] + b3v;
            }
    }
}

// ---------------- k3: tril softmax ----------------
__global__ void k3_softmax(float* __restrict__ out) {
    const int i = blockIdx.x, b = blockIdx.y, j = threadIdx.x;
    float val;
    if (j < i)       val = g_S[((size_t)b * 192 + i) * 192 + j];
    else if (j == i) val = 0.f;
    else             val = -1e30f;

    __shared__ float red[6];
    float m = val;
#pragma unroll
    for (int o = 16; o; o >>= 1) m = fmaxf(m, __shfl_xor_sync(0xffffffffu, m, o));
    if ((j & 31) == 0) red[j >> 5] = m;
    __syncthreads();
    float M = fmaxf(fmaxf(fmaxf(red[0], red[1]), fmaxf(red[2], red[3])), fmaxf(red[4], red[5]));
    __syncthreads();
    float e = (j <= i) ? expf(val - M) : 0.f;
    float s = e;
#pragma unroll
    for (int o = 16; o; o >>= 1) s += __shfl_xor_sync(0xffffffffu, s, o);
    if ((j & 31) == 0) red[j >> 5] = s;
    __syncthreads();
    float S = red[0] + red[1] + red[2] + red[3] + red[4] + red[5];
    out[((size_t)b * 192 + i) * 192 + j] = (j <= i) ? (e / S) : -1000.0f;
}

// ---------------------------------------------------------------------------
extern "C" void kernel_launch(void* const* d_in, const int* in_sizes, int n_in,
                              void* d_out, int out_size) {
    const float* E  = (const float*)d_in[0];
    const float* W1 = (const float*)d_in[1];
    const float* b1 = (const float*)d_in[2];
    const float* W2 = (const float*)d_in[3];
    const float* b2 = (const float*)d_in[4];
    const float* W3 = (const float*)d_in[5];
    const float* b3 = (const float*)d_in[6];
    float* out = (float*)d_out;

    cudaFuncSetAttribute(k1_mma, cudaFuncAttributeMaxDynamicSharedMemorySize, K1_SMEM);
    cudaFuncSetAttribute(k2_mma, cudaFuncAttributeMaxDynamicSharedMemorySize, K2_SMEM);

    kprep_e<<<(1536 * EPITCH + 255) / 256, 256>>>(E);
    kprep_w<<<(WAB_N + W1CP_N + W2_W + 255) / 256, 256>>>(W1, W2);
    k1_mma<<<48, 256, K1_SMEM>>>(b1);
    k2_mma<<<dim3(12, 24, 8), 256, K2_SMEM>>>(b2, W3, b3);
    k3_softmax<<<dim3(192, 8), 192>>>(out);
}